// round 11
// baseline (speedup 1.0000x reference)
#include <cuda_runtime.h>
#include <cuda_bf16.h>
#include <cuda_fp16.h>
#include <math.h>

// ---------------------------------------------------------------------------
// LSTM: S=512, B=64, I=256, H=512
// out = [h_seq (S,B,H) | h_final (B,H) | c_final (B,H)]  (fp32)
// Fully fused: one persistent mma.sync kernel does Wx*x_t (in the barrier
// shadow) + Wh*h (critical path). x and h as fp16 hi+lo 2-pass (~fp32).
// ---------------------------------------------------------------------------

#define S_LEN 512
#define BATCH 64
#define IN_DIM 256
#define HID 512
#define G4 2048              // 4*H
#define BH (BATCH*HID)       // 32768
#define NCTA 128
#define BST 520              // h smem row stride (halves)
#define XST 264              // x/Wx smem row stride (halves)

// smem offsets (in halves)
#define WXS_OFF 0            // Wx slice: 64 x XST
#define XB_OFF  16896        // x buffers: [2 parity][hi,lo] 16 x XST each
#define XB_PAR  8448         // halves per parity block (hi+lo)
#define XB_HL   4224         // halves per hi or lo block
#define BHI_OFF 33792        // h hi: 16 x BST
#define BLO_OFF 42112        // h lo: 16 x BST
#define RG_OFFH 50432        // rg floats start here (half-offset)
#define REC_SMEM (50432*2 + 64*17*4)   // 105216 bytes

// -------------------- device scratch (static: no allocs allowed) ------------
__device__ __half g_WxT[(size_t)G4 * IN_DIM];        // WxT[n][k] fp16
__device__ float  g_WhT[(size_t)G4 * HID];           // WhT[col][k]
__device__ float  g_bias[G4];                        // bx + bh
__device__ __half g_xh[(size_t)S_LEN * BATCH * IN_DIM];  // x hi fp16
__device__ __half g_xl[(size_t)S_LEN * BATCH * IN_DIM];  // x lo fp16
__device__ __half g_hh[2][BH];                       // h hi fp16, ping-pong
__device__ __half g_hl[2][BH];                       // h lo fp16, ping-pong
__device__ unsigned int g_barc[4 * 32];              // per-bg counters

// fast activations
__device__ __forceinline__ float fast_exp(float x) {
    float e;
    asm("ex2.approx.f32 %0, %1;" : "=f"(e) : "f"(x * 1.4426950408889634f));
    return e;
}
__device__ __forceinline__ float fast_rcp(float x) {
    float r;
    asm("rcp.approx.f32 %0, %1;" : "=f"(r) : "f"(x));
    return r;
}
__device__ __forceinline__ float fast_sigmoid(float x) {
    return fast_rcp(1.f + fast_exp(-x));
}
__device__ __forceinline__ float fast_tanh(float x) {
    return 2.f * fast_rcp(1.f + fast_exp(-2.f * x)) - 1.f;
}

__device__ __forceinline__ void cpasync16(unsigned dst, const void* src) {
    asm volatile("cp.async.cg.shared.global [%0], [%1], 16;"
                 :: "r"(dst), "l"(src));
}

// mma.sync m16n8k16 row.col f32.f16.f16.f32 (accumulate in place)
__device__ __forceinline__ void hmma16816(float& d0, float& d1, float& d2, float& d3,
                                          unsigned a0, unsigned a1, unsigned a2, unsigned a3,
                                          unsigned b0, unsigned b1) {
    asm volatile(
        "mma.sync.aligned.m16n8k16.row.col.f32.f16.f16.f32 "
        "{%0,%1,%2,%3}, {%4,%5,%6,%7}, {%8,%9}, {%0,%1,%2,%3};"
        : "+f"(d0), "+f"(d1), "+f"(d2), "+f"(d3)
        : "r"(a0), "r"(a1), "r"(a2), "r"(a3), "r"(b0), "r"(b1));
}

// -------------------- merged prep kernel --------------------------------------
// grid covers S*B*I = 8.4M (x hi/lo convert) plus all weight packs.
__global__ void prep_kernel(
    const float* __restrict__ x,
    const float* __restrict__ Wxf, const float* __restrict__ Wxi,
    const float* __restrict__ Wxo, const float* __restrict__ Wxg,
    const float* __restrict__ Whf, const float* __restrict__ Whi,
    const float* __restrict__ Who, const float* __restrict__ Whg,
    const float* __restrict__ bxf, const float* __restrict__ bhf,
    const float* __restrict__ bxi, const float* __restrict__ bhi,
    const float* __restrict__ bxo, const float* __restrict__ bho,
    const float* __restrict__ bxg, const float* __restrict__ bhg)
{
    int idx = blockIdx.x * blockDim.x + threadIdx.x;

    if (idx < 4 * 32) g_barc[idx] = 0u;

    if (idx < G4) {
        int g = idx >> 9, jj = idx & 511;
        const float* bx = (g == 0) ? bxf : (g == 1) ? bxi : (g == 2) ? bxo : bxg;
        const float* bh = (g == 0) ? bhf : (g == 1) ? bhi : (g == 2) ? bho : bhg;
        g_bias[idx] = bx[jj] + bh[jj];
    }

    if (idx < G4 * IN_DIM) {         // g_WxT[n][k] = Wx_gate[k][unit] fp16
        int n = idx >> 8;
        int k = idx & 255;
        int g = n >> 9, unit = n & 511;
        const float* W = (g == 0) ? Wxf : (g == 1) ? Wxi : (g == 2) ? Wxo : Wxg;
        g_WxT[idx] = __float2half_rn(W[k * HID + unit]);
    }

    if (idx < G4 * HID) {
        int col = idx >> 9;
        int k   = idx & 511;
        int g   = col >> 9;
        int jj  = col & 511;
        const float* W = (g == 0) ? Whf : (g == 1) ? Whi : (g == 2) ? Who : Whg;
        g_WhT[idx] = W[k * HID + jj];   // WhT[col][k] = Wh[k][col]
    }

    if (idx < S_LEN * BATCH * IN_DIM) {   // x -> hi/lo fp16
        float v = x[idx];
        __half hi = __float2half_rn(v);
        g_xh[idx] = hi;
        g_xl[idx] = __float2half_rn(v - __half2float(hi));
    }
}

// -------------------- fused recurrence ----------------------------------------
// 128 CTAs = 4 bg (16 batches) x 32 ug (16 units). 256 threads = 8 warps.
// Warp w: mt=w>>1 (gate-rows mt*16..+15), nt=w&1 (batches nt*8..+7).
// Wh fp16 A-frags in REGISTERS (32 ks x 4); Wx fp16 A-tile in smem (static).
// Per step: dacc holds Wx*x_t (computed last step, in barrier shadow);
// stage h(t-1) hi/lo + x(t+1) hi/lo via cp.async; dacc += Wh*h (hi+lo);
// regroup -> fp32 activations (c in regs, bias in regs); after activation,
// compute Wx*x_{t+1} into dacc; group barrier.
__global__ __launch_bounds__(256, 1) void lstm_rec_kernel(float* __restrict__ out)
{
    extern __shared__ __half sh[];
    __half* wxs = sh + WXS_OFF;
    float*  rg  = (float*)(sh + RG_OFFH);

    const int tid  = threadIdx.x;
    const int w    = tid >> 5;
    const int lane = tid & 31;
    const int g    = lane >> 2;
    const int tq   = lane & 3;
    const int mt   = w >> 1;
    const int nt   = w & 1;
    const int cta  = blockIdx.x;
    const int ug   = cta & 31;        // units [ug*16, +16)
    const int bg   = cta >> 5;        // batches [bg*16, +16)

    const unsigned sb = (unsigned)__cvta_generic_to_shared(sh);

    // ---- Wh A-fragments (registers, once) ----
    unsigned ar[32][4];
#pragma unroll
    for (int ks = 0; ks < 32; ks++) {
#pragma unroll
        for (int j = 0; j < 4; j++) {
            int row  = mt * 16 + g + ((j & 1) << 3);
            int k    = ks * 16 + tq * 2 + ((j >> 1) << 3);
            int wcol = (row >> 4) * HID + (ug << 4) + (row & 15);
            float v0 = g_WhT[(size_t)wcol * HID + k];
            float v1 = g_WhT[(size_t)wcol * HID + k + 1];
            __half2 hv = __floats2half2_rn(v0, v1);
            ar[ks][j] = *(unsigned*)&hv;
        }
    }

    // ---- Wx A-tile -> smem (once): wxs[r][k], r = gate*16+unit local row ----
    for (int i = 0; i < 8; i++) {
        int c  = tid + (i << 8);                 // 2048 chunks of 8 halves
        int r  = c >> 5;
        int ko = (c & 31) << 3;
        int n  = (r >> 4) * HID + (ug << 4) + (r & 15);
        *(uint4*)&wxs[r * XST + ko] = *(const uint4*)&g_WxT[(size_t)n * IN_DIM + ko];
    }

    // ---- stage x(0) ----
    {
        const __half* s_hi = g_xh + (size_t)(bg * 16) * IN_DIM;
        const __half* s_lo = g_xl + (size_t)(bg * 16) * IN_DIM;
#pragma unroll
        for (int i = 0; i < 4; i++) {            // 1024 chunks / 256 thr
            int idx  = tid + (i << 8);
            int buf  = idx >> 9;
            int rem  = idx & 511;
            int lrow = rem >> 5;
            int ch   = rem & 31;
            const __half* src = (buf ? s_lo : s_hi) + lrow * IN_DIM + (ch << 3);
            unsigned dst = sb + (unsigned)(XB_OFF + buf * XB_HL
                                           + lrow * XST + (ch << 3)) * 2u;
            cpasync16(dst, (const void*)src);
        }
        asm volatile("cp.async.commit_group;");
        asm volatile("cp.async.wait_group 0;" ::: "memory");
    }
    __syncthreads();

    // fragment pointers
    const __half* wxp = wxs + (mt * 16 + g) * XST + tq * 2;   // Wx A-frags
    const __half* bhr = sh + BHI_OFF + (nt * 8 + g) * BST + tq * 2;
    const __half* blr = sh + BLO_OFF + (nt * 8 + g) * BST + tq * 2;

    const unsigned shi = sb + (unsigned)BHI_OFF * 2u;
    const unsigned slo = sb + (unsigned)BLO_OFF * 2u;

    // ---- xp MMA for t=0 into dacc ----
    float d0, d1, d2, d3;
#define XP_MMA(PAR)                                                           \
    do {                                                                      \
        const __half* xbh = sh + XB_OFF + (PAR) * XB_PAR + (nt * 8 + g) * XST + tq * 2; \
        const __half* xbl = xbh + XB_HL;                                      \
        d0 = d1 = d2 = d3 = 0.f;                                              \
        _Pragma("unroll")                                                     \
        for (int ks = 0; ks < 16; ks++) {                                     \
            unsigned A0 = *(const unsigned*)(wxp + ks * 16);                  \
            unsigned A1 = *(const unsigned*)(wxp + ks * 16 + 8 * XST);        \
            unsigned A2 = *(const unsigned*)(wxp + ks * 16 + 8);              \
            unsigned A3 = *(const unsigned*)(wxp + ks * 16 + 8 * XST + 8);    \
            unsigned B0h = *(const unsigned*)(xbh + ks * 16);                 \
            unsigned B1h = *(const unsigned*)(xbh + ks * 16 + 8);             \
            unsigned B0l = *(const unsigned*)(xbl + ks * 16);                 \
            unsigned B1l = *(const unsigned*)(xbl + ks * 16 + 8);             \
            hmma16816(d0, d1, d2, d3, A0, A1, A2, A3, B0h, B1h);              \
            hmma16816(d0, d1, d2, d3, A0, A1, A2, A3, B0l, B1l);              \
        }                                                                     \
    } while (0)

    XP_MMA(0);

    // ---- activation mapping + bias in registers ----
    const int ab = tid >> 4;
    const int au = tid & 15;
    const int gb = bg * 16 + ab;
    const int gj = (ug << 4) + au;
    const float bsf = g_bias[gj];
    const float bsi = g_bias[gj + 512];
    const float bso = g_bias[gj + 1024];
    const float bsg = g_bias[gj + 1536];

    unsigned int* barp = &g_barc[bg * 32];
    float cval = 0.f;

    for (int t = 0; t < S_LEN; t++) {
        const bool has_next = (t + 1 < S_LEN);

        if (t > 0) {
            // ---- stage h(t-1) hi/lo (group H) ----
            const int pp = (t - 1) & 1;
            const __half* s_hi = g_hh[pp] + (size_t)(bg * 16) * HID;
            const __half* s_lo = g_hl[pp] + (size_t)(bg * 16) * HID;
#pragma unroll
            for (int i = 0; i < 8; i++) {
                int idx  = tid + (i << 8);
                int buf  = idx >> 10;
                int rem  = idx & 1023;
                int lrow = rem >> 6;
                int ch   = rem & 63;
                const __half* src = (buf ? s_lo : s_hi) + lrow * HID + (ch << 3);
                unsigned dst = (buf ? slo : shi)
                               + (unsigned)(lrow * BST + (ch << 3)) * 2u;
                cpasync16(dst, (const void*)src);
            }
            asm volatile("cp.async.commit_group;");
        }

        if (has_next) {
            // ---- stage x(t+1) hi/lo (group X) ----
            const __half* s_hi = g_xh + ((size_t)(t + 1) * BATCH + bg * 16) * IN_DIM;
            const __half* s_lo = g_xl + ((size_t)(t + 1) * BATCH + bg * 16) * IN_DIM;
            const int par = (t + 1) & 1;
#pragma unroll
            for (int i = 0; i < 4; i++) {
                int idx  = tid + (i << 8);
                int buf  = idx >> 9;
                int rem  = idx & 511;
                int lrow = rem >> 5;
                int ch   = rem & 31;
                const __half* src = (buf ? s_lo : s_hi) + lrow * IN_DIM + (ch << 3);
                unsigned dst = sb + (unsigned)(XB_OFF + par * XB_PAR + buf * XB_HL
                                               + lrow * XST + (ch << 3)) * 2u;
                cpasync16(dst, (const void*)src);
            }
            asm volatile("cp.async.commit_group;");
        }

        if (t > 0) {
            // wait for H (X may still be in flight)
            if (has_next)
                asm volatile("cp.async.wait_group 1;" ::: "memory");
            else
                asm volatile("cp.async.wait_group 0;" ::: "memory");
            __syncthreads();

            // ---- Wh MMA: dacc += Wh*h_hi + Wh*h_lo ----
#pragma unroll
            for (int ks = 0; ks < 32; ks++) {
                unsigned b0h = *(const unsigned*)(bhr + ks * 16);
                unsigned b1h = *(const unsigned*)(bhr + ks * 16 + 8);
                unsigned b0l = *(const unsigned*)(blr + ks * 16);
                unsigned b1l = *(const unsigned*)(blr + ks * 16 + 8);
                hmma16816(d0, d1, d2, d3,
                          ar[ks][0], ar[ks][1], ar[ks][2], ar[ks][3], b0h, b1h);
                hmma16816(d0, d1, d2, d3,
                          ar[ks][0], ar[ks][1], ar[ks][2], ar[ks][3], b0l, b1l);
            }
        }

        // ---- regroup dacc -> rg ----
        {
            int row = mt * 16 + g;
            int col = nt * 8 + tq * 2;
            rg[row * 17 + col]           = d0;
            rg[row * 17 + col + 1]       = d1;
            rg[(row + 8) * 17 + col]     = d2;
            rg[(row + 8) * 17 + col + 1] = d3;
        }
        __syncthreads();

        // ---- activation: thread (ab, au) ----
        float gf = rg[(au +  0) * 17 + ab] + bsf;
        float gi = rg[(au + 16) * 17 + ab] + bsi;
        float go = rg[(au + 32) * 17 + ab] + bso;
        float gg = rg[(au + 48) * 17 + ab] + bsg;

        float fg = fast_sigmoid(gf);
        float ig = fast_sigmoid(gi);
        float og = fast_sigmoid(go);
        float gt = fast_tanh(gg);
        cval = fg * cval + ig * gt;
        float hval = og * fast_tanh(cval);

        out[(size_t)t * BH + (size_t)gb * HID + gj] = hval;
        if (has_next) {
            const int p = t & 1;
            __half hi = __float2half_rn(hval);
            __half lo = __float2half_rn(hval - __half2float(hi));
            g_hh[p][(size_t)gb * HID + gj] = hi;
            g_hl[p][(size_t)gb * HID + gj] = lo;

            // ---- xp MMA for t+1 (barrier shadow) ----
            asm volatile("cp.async.wait_group 0;" ::: "memory");
            __syncthreads();
            XP_MMA((t + 1) & 1);

            // ---- per-bg barrier: 32 arrivals ----
            __syncthreads();
            if (tid == 0) {
                asm volatile("red.release.gpu.global.add.u32 [%0], 1;"
                             :: "l"(barp) : "memory");
                unsigned target = (unsigned)(t + 1) * 32u;
                unsigned v;
                while (true) {
                    asm volatile("ld.acquire.gpu.global.u32 %0, [%1];"
                                 : "=r"(v) : "l"(barp) : "memory");
                    if (v >= target) break;
                    __nanosleep(20);
                }
            }
            __syncthreads();
        } else {
            out[(size_t)S_LEN * BH + (size_t)gb * HID + gj] = hval;        // h_f
            out[(size_t)S_LEN * BH + BH + (size_t)gb * HID + gj] = cval;   // c_f
        }
    }
#undef XP_MMA
}

// -------------------- launch ------------------------------------------------
extern "C" void kernel_launch(void* const* d_in, const int* in_sizes, int n_in,
                              void* d_out, int out_size)
{
    (void)in_sizes; (void)n_in; (void)out_size;
    const float* x   = (const float*)d_in[0];
    const float* Wxf = (const float*)d_in[1];
    const float* bxf = (const float*)d_in[2];
    const float* Whf = (const float*)d_in[3];
    const float* bhf = (const float*)d_in[4];
    const float* Wxi = (const float*)d_in[5];
    const float* bxi = (const float*)d_in[6];
    const float* Whi = (const float*)d_in[7];
    const float* bhi = (const float*)d_in[8];
    const float* Wxo = (const float*)d_in[9];
    const float* bxo = (const float*)d_in[10];
    const float* Who = (const float*)d_in[11];
    const float* bho = (const float*)d_in[12];
    const float* Wxg = (const float*)d_in[13];
    const float* bxg = (const float*)d_in[14];
    const float* Whg = (const float*)d_in[15];
    const float* bhg = (const float*)d_in[16];
    float* out = (float*)d_out;

    // grid covers x conversion (8.4M) and all packs
    prep_kernel<<<(S_LEN * BATCH * IN_DIM + 255) / 256, 256>>>(
        x, Wxf, Wxi, Wxo, Wxg, Whf, Whi, Who, Whg,
        bxf, bhf, bxi, bhi, bxo, bho, bxg, bhg);

    static bool attr_set = false;
    if (!attr_set) {
        cudaFuncSetAttribute(lstm_rec_kernel,
                             cudaFuncAttributeMaxDynamicSharedMemorySize, REC_SMEM);
        attr_set = true;
    }
    lstm_rec_kernel<<<NCTA, 256, REC_SMEM>>>(out);
}

// round 12
// speedup vs baseline: 1.0664x; 1.0664x over previous
#include <cuda_runtime.h>
#include <cuda_bf16.h>
#include <cuda_fp16.h>
#include <math.h>

// ---------------------------------------------------------------------------
// LSTM: S=512, B=64, I=256, H=512
// out = [h_seq (S,B,H) | h_final (B,H) | c_final (B,H)]  (fp32)
// xproj + recurrence both on mma.sync m16n8k16 (hi/lo fp16 splits ~ fp32).
// ---------------------------------------------------------------------------

#define S_LEN 512
#define BATCH 64
#define IN_DIM 256
#define HID 512
#define G4 2048              // 4*H
#define BH (BATCH*HID)       // 32768
#define BG (BATCH*G4)        // 131072
#define NCTA 128
#define BST 520              // rec B smem row stride (halves)

// xproj tiling: 64x128 CTA tile, warp tile 32x32, 2 CTAs/SM
#define XM 64
#define XN 128
#define XBK 32
#define XST 40               // xproj smem row stride (halves): 20 words/row
#define XA_BUF (XM*XST)      // 2560 halves per A buffer
#define XB_BUF (XN*XST)      // 5120 halves per B buffer
#define XP_SMEM ((4*XA_BUF + 2*XB_BUF) * 2)   // 40960 bytes

// -------------------- device scratch (static: no allocs allowed) ------------
__device__ float  g_xp[(size_t)S_LEN * BATCH * G4];  // x@Wx + bx + bh
__device__ __half g_WxT[(size_t)G4 * IN_DIM];        // WxT[n][k] fp16
__device__ float  g_WhT[(size_t)G4 * HID];           // WhT[col][k]
__device__ float  g_bias[G4];                        // bx + bh
__device__ __half g_hh[2][BH];                       // h hi fp16, ping-pong
__device__ __half g_hl[2][BH];                       // h lo fp16, ping-pong
__device__ unsigned int g_barc[4 * 32];              // per-bg counters

// fast activations
__device__ __forceinline__ float fast_exp(float x) {
    float e;
    asm("ex2.approx.f32 %0, %1;" : "=f"(e) : "f"(x * 1.4426950408889634f));
    return e;
}
__device__ __forceinline__ float fast_rcp(float x) {
    float r;
    asm("rcp.approx.f32 %0, %1;" : "=f"(r) : "f"(x));
    return r;
}
__device__ __forceinline__ float fast_sigmoid(float x) {
    return fast_rcp(1.f + fast_exp(-x));
}
__device__ __forceinline__ float fast_tanh(float x) {
    return 2.f * fast_rcp(1.f + fast_exp(-2.f * x)) - 1.f;
}

__device__ __forceinline__ void cpasync16(unsigned dst, const void* src) {
    asm volatile("cp.async.cg.shared.global [%0], [%1], 16;"
                 :: "r"(dst), "l"(src));
}

// mma.sync m16n8k16 row.col f32.f16.f16.f32 (accumulate in place)
__device__ __forceinline__ void hmma16816(float& d0, float& d1, float& d2, float& d3,
                                          unsigned a0, unsigned a1, unsigned a2, unsigned a3,
                                          unsigned b0, unsigned b1) {
    asm volatile(
        "mma.sync.aligned.m16n8k16.row.col.f32.f16.f16.f32 "
        "{%0,%1,%2,%3}, {%4,%5,%6,%7}, {%8,%9}, {%0,%1,%2,%3};"
        : "+f"(d0), "+f"(d1), "+f"(d2), "+f"(d3)
        : "r"(a0), "r"(a1), "r"(a2), "r"(a3), "r"(b0), "r"(b1));
}

// -------------------- merged prep kernel --------------------------------------
__global__ void prep_kernel(
    const float* __restrict__ Wxf, const float* __restrict__ Wxi,
    const float* __restrict__ Wxo, const float* __restrict__ Wxg,
    const float* __restrict__ Whf, const float* __restrict__ Whi,
    const float* __restrict__ Who, const float* __restrict__ Whg,
    const float* __restrict__ bxf, const float* __restrict__ bhf,
    const float* __restrict__ bxi, const float* __restrict__ bhi,
    const float* __restrict__ bxo, const float* __restrict__ bho,
    const float* __restrict__ bxg, const float* __restrict__ bhg)
{
    int idx = blockIdx.x * blockDim.x + threadIdx.x;

    if (idx < 4 * 32) g_barc[idx] = 0u;

    if (idx < G4) {
        int g = idx >> 9, jj = idx & 511;
        const float* bx = (g == 0) ? bxf : (g == 1) ? bxi : (g == 2) ? bxo : bxg;
        const float* bh = (g == 0) ? bhf : (g == 1) ? bhi : (g == 2) ? bho : bhg;
        g_bias[idx] = bx[jj] + bh[jj];
    }

    if (idx < G4 * IN_DIM) {         // g_WxT[n][k] = Wx_gate[k][unit] fp16
        int n = idx >> 8;
        int k = idx & 255;
        int g = n >> 9, unit = n & 511;
        const float* W = (g == 0) ? Wxf : (g == 1) ? Wxi : (g == 2) ? Wxo : Wxg;
        g_WxT[idx] = __float2half_rn(W[k * HID + unit]);
    }

    if (idx < G4 * HID) {
        int col = idx >> 9;
        int k   = idx & 511;
        int g   = col >> 9;
        int jj  = col & 511;
        const float* W = (g == 0) ? Whf : (g == 1) ? Whi : (g == 2) ? Who : Whg;
        g_WhT[idx] = W[k * HID + jj];   // WhT[col][k] = Wh[k][col]
    }
}

// -------------------- xproj via mma.sync ---------------------------------------
// xp[m][n] = sum_k x[m][k]*Wx[k][n] + bias[n].
// CTA tile 64x128, BK=32, 8 warps (2 m-tiles x 4 n-tiles of 32x32).
// A = x as hi+lo fp16 (2 passes ~ fp32); B = WxT fp16 (single).
// Double-buffered smem; B via cp.async, A via LDG->convert->STS. 2 CTAs/SM.
__global__ __launch_bounds__(256, 2) void xproj_hmma(const float* __restrict__ x)
{
    extern __shared__ __half xs[];
    __half* a_hi = xs;                       // 2 x XA_BUF
    __half* a_lo = xs + 2 * XA_BUF;          // 2 x XA_BUF
    __half* bsm  = xs + 4 * XA_BUF;          // 2 x XB_BUF

    const int tid  = threadIdx.x;
    const int w    = tid >> 5;
    const int lane = tid & 31;
    const int g    = lane >> 2;
    const int tq   = lane & 3;
    const int mw   = w >> 2;                 // 0..1
    const int nw   = w & 3;                  // 0..3
    const int bm   = blockIdx.y * XM;
    const int bn   = blockIdx.x * XN;

    const int arow = tid >> 2;               // 0..63
    const int aq   = tid & 3;                // k-chunk of 8 floats
    const float* axp = x + (size_t)(bm + arow) * IN_DIM + aq * 8;

    const unsigned sb   = (unsigned)__cvta_generic_to_shared(xs);
    const unsigned bsmb = sb + (unsigned)(4 * XA_BUF) * 2u;

    float acc[2][4][4];
#pragma unroll
    for (int f = 0; f < 2; f++)
#pragma unroll
        for (int nf = 0; nf < 4; nf++)
#pragma unroll
            for (int q = 0; q < 4; q++) acc[f][nf][q] = 0.f;

#define CPB(p, ktg)                                                          \
    do {                                                                     \
        _Pragma("unroll")                                                    \
        for (int i = 0; i < 2; i++) {                                        \
            int idx = tid + (i << 8);                                        \
            int n   = idx >> 2;                                              \
            int ko  = (idx & 3) << 3;                                        \
            unsigned dst = bsmb + (unsigned)((p) * XB_BUF + n * XST + ko) * 2u; \
            cpasync16(dst, (const void*)(g_WxT + (size_t)(bn + n) * IN_DIM + (ktg) + ko)); \
        }                                                                    \
    } while (0)

#define STAGEA(p, v0, v1)                                                    \
    do {                                                                     \
        float ff[8] = {v0.x, v0.y, v0.z, v0.w, v1.x, v1.y, v1.z, v1.w};      \
        __align__(16) __half hh[8];                                          \
        __align__(16) __half hl[8];                                          \
        _Pragma("unroll")                                                    \
        for (int i = 0; i < 8; i++) {                                        \
            hh[i] = __float2half_rn(ff[i]);                                  \
            hl[i] = __float2half_rn(ff[i] - __half2float(hh[i]));            \
        }                                                                    \
        *(uint4*)(a_hi + (p) * XA_BUF + arow * XST + aq * 8) = *(uint4*)hh;  \
        *(uint4*)(a_lo + (p) * XA_BUF + arow * XST + aq * 8) = *(uint4*)hl;  \
    } while (0)

    // ---- prologue: tile 0 ----
    {
        CPB(0, 0);
        asm volatile("cp.async.commit_group;");
        float4 v0 = *(const float4*)(axp);
        float4 v1 = *(const float4*)(axp + 4);
        STAGEA(0, v0, v1);
        asm volatile("cp.async.wait_group 0;" ::: "memory");
    }
    __syncthreads();

#pragma unroll
    for (int kt = 0; kt < IN_DIM / XBK; kt++) {
        const int p = kt & 1;
        const bool has_next = (kt + 1) < (IN_DIM / XBK);

        float4 nv0, nv1;
        if (has_next) {
            CPB(p ^ 1, (kt + 1) * XBK);
            asm volatile("cp.async.commit_group;");
            nv0 = *(const float4*)(axp + (kt + 1) * XBK);
            nv1 = *(const float4*)(axp + (kt + 1) * XBK + 4);
        }

        const __half* ah_p = a_hi + p * XA_BUF;
        const __half* al_p = a_lo + p * XA_BUF;
        const __half* b_p  = bsm + p * XB_BUF;

#pragma unroll
        for (int ks = 0; ks < 2; ks++) {
            unsigned AH[2][4], AL[2][4], BB[4][2];
#pragma unroll
            for (int f = 0; f < 2; f++)
#pragma unroll
                for (int j = 0; j < 4; j++) {
                    int row = mw * 32 + f * 16 + g + ((j & 1) << 3);
                    int k   = ks * 16 + tq * 2 + ((j >> 1) << 3);
                    AH[f][j] = *(const unsigned*)(ah_p + row * XST + k);
                    AL[f][j] = *(const unsigned*)(al_p + row * XST + k);
                }
#pragma unroll
            for (int nf = 0; nf < 4; nf++) {
                int n = nw * 32 + nf * 8 + g;
                BB[nf][0] = *(const unsigned*)(b_p + n * XST + ks * 16 + tq * 2);
                BB[nf][1] = *(const unsigned*)(b_p + n * XST + ks * 16 + tq * 2 + 8);
            }
#pragma unroll
            for (int f = 0; f < 2; f++)
#pragma unroll
                for (int nf = 0; nf < 4; nf++) {
                    hmma16816(acc[f][nf][0], acc[f][nf][1], acc[f][nf][2], acc[f][nf][3],
                              AH[f][0], AH[f][1], AH[f][2], AH[f][3],
                              BB[nf][0], BB[nf][1]);
                    hmma16816(acc[f][nf][0], acc[f][nf][1], acc[f][nf][2], acc[f][nf][3],
                              AL[f][0], AL[f][1], AL[f][2], AL[f][3],
                              BB[nf][0], BB[nf][1]);
                }
        }

        if (has_next) {
            STAGEA(p ^ 1, nv0, nv1);
            asm volatile("cp.async.wait_group 0;" ::: "memory");
            __syncthreads();
        }
    }

    // ---- epilogue: bias add + store ----
#pragma unroll
    for (int nf = 0; nf < 4; nf++) {
        int col = bn + nw * 32 + nf * 8 + tq * 2;
        float b0 = g_bias[col];
        float b1 = g_bias[col + 1];
#pragma unroll
        for (int f = 0; f < 2; f++) {
            int r0 = bm + mw * 32 + f * 16 + g;
            float2 o0 = make_float2(acc[f][nf][0] + b0, acc[f][nf][1] + b1);
            float2 o1 = make_float2(acc[f][nf][2] + b0, acc[f][nf][3] + b1);
            *(float2*)&g_xp[(size_t)r0 * G4 + col]       = o0;
            *(float2*)&g_xp[(size_t)(r0 + 8) * G4 + col] = o1;
        }
    }
#undef CPB
#undef STAGEA
}

// -------------------- recurrence: mma.sync persistent (unchanged R9/R10) ------
__global__ __launch_bounds__(256, 1) void lstm_rec_kernel(float* __restrict__ out)
{
    __shared__ __align__(16) __half b_hi[16 * BST];
    __shared__ __align__(16) __half b_lo[16 * BST];
    __shared__ float rg[64 * 17];

    const int tid  = threadIdx.x;
    const int w    = tid >> 5;
    const int lane = tid & 31;
    const int g    = lane >> 2;
    const int tq   = lane & 3;
    const int mt   = w >> 1;
    const int nt   = w & 1;
    const int cta  = blockIdx.x;
    const int ug   = cta & 31;
    const int bg   = cta >> 5;

    unsigned ar[32][4];
#pragma unroll
    for (int ks = 0; ks < 32; ks++) {
#pragma unroll
        for (int j = 0; j < 4; j++) {
            int row  = mt * 16 + g + ((j & 1) << 3);
            int k    = ks * 16 + tq * 2 + ((j >> 1) << 3);
            int wcol = (row >> 4) * HID + (ug << 4) + (row & 15);
            float v0 = g_WhT[(size_t)wcol * HID + k];
            float v1 = g_WhT[(size_t)wcol * HID + k + 1];
            __half2 hv = __floats2half2_rn(v0, v1);
            ar[ks][j] = *(unsigned*)&hv;
        }
    }

    const __half* bhr = b_hi + (nt * 8 + g) * BST + tq * 2;
    const __half* blr = b_lo + (nt * 8 + g) * BST + tq * 2;

    const unsigned shi = (unsigned)__cvta_generic_to_shared(b_hi);
    const unsigned slo = (unsigned)__cvta_generic_to_shared(b_lo);

    const int ab = tid >> 4;
    const int au = tid & 15;
    const int gb = bg * 16 + ab;
    const int gj = (ug << 4) + au;

    unsigned int* barp = &g_barc[bg * 32];

    const size_t xof = (size_t)gb * G4 + gj;
    float c0 = g_xp[xof];
    float c1 = g_xp[xof + 512];
    float c2 = g_xp[xof + 1024];
    float c3 = g_xp[xof + 1536];

    float cval = 0.f;

    for (int t = 0; t < S_LEN; t++) {
        if (t > 0) {
            const int pp = (t - 1) & 1;
            const __half* s_hi = g_hh[pp] + (size_t)(bg * 16) * HID;
            const __half* s_lo = g_hl[pp] + (size_t)(bg * 16) * HID;
#pragma unroll
            for (int i = 0; i < 8; i++) {
                int idx  = tid + (i << 8);
                int buf  = idx >> 10;
                int rem  = idx & 1023;
                int lrow = rem >> 6;
                int ch   = rem & 63;
                const __half* src = (buf ? s_lo : s_hi) + lrow * HID + (ch << 3);
                unsigned dst = (buf ? slo : shi)
                               + (unsigned)(lrow * BST + (ch << 3)) * 2u;
                cpasync16(dst, (const void*)src);
            }
            asm volatile("cp.async.commit_group;");
            asm volatile("cp.async.wait_group 0;" ::: "memory");
            __syncthreads();
        }

        float n0 = 0.f, n1 = 0.f, n2 = 0.f, n3 = 0.f;
        if (t + 1 < S_LEN) {
            size_t nb = (size_t)(t + 1) * BG + xof;
            n0 = g_xp[nb]; n1 = g_xp[nb + 512];
            n2 = g_xp[nb + 1024]; n3 = g_xp[nb + 1536];
        }

        if (t > 0) {
            float d0 = 0.f, d1 = 0.f, d2 = 0.f, d3 = 0.f;
#pragma unroll
            for (int ks = 0; ks < 32; ks++) {
                unsigned b0h = *(const unsigned*)(bhr + ks * 16);
                unsigned b1h = *(const unsigned*)(bhr + ks * 16 + 8);
                unsigned b0l = *(const unsigned*)(blr + ks * 16);
                unsigned b1l = *(const unsigned*)(blr + ks * 16 + 8);
                hmma16816(d0, d1, d2, d3,
                          ar[ks][0], ar[ks][1], ar[ks][2], ar[ks][3], b0h, b1h);
                hmma16816(d0, d1, d2, d3,
                          ar[ks][0], ar[ks][1], ar[ks][2], ar[ks][3], b0l, b1l);
            }
            int row = mt * 16 + g;
            int col = nt * 8 + tq * 2;
            rg[row * 17 + col]           = d0;
            rg[row * 17 + col + 1]       = d1;
            rg[(row + 8) * 17 + col]     = d2;
            rg[(row + 8) * 17 + col + 1] = d3;
            __syncthreads();
        }

        float gf = c0, gi = c1, go = c2, gg = c3;
        if (t > 0) {
            gf += rg[(au +  0) * 17 + ab];
            gi += rg[(au + 16) * 17 + ab];
            go += rg[(au + 32) * 17 + ab];
            gg += rg[(au + 48) * 17 + ab];
        }
        c0 = n0; c1 = n1; c2 = n2; c3 = n3;

        float fg = fast_sigmoid(gf);
        float ig = fast_sigmoid(gi);
        float og = fast_sigmoid(go);
        float gt = fast_tanh(gg);
        cval = fg * cval + ig * gt;
        float hval = og * fast_tanh(cval);

        out[(size_t)t * BH + (size_t)gb * HID + gj] = hval;
        {
            const int p = t & 1;
            __half hi = __float2half_rn(hval);
            __half lo = __float2half_rn(hval - __half2float(hi));
            g_hh[p][(size_t)gb * HID + gj] = hi;
            g_hl[p][(size_t)gb * HID + gj] = lo;
        }

        if (t < S_LEN - 1) {
            __syncthreads();
            if (tid == 0) {
                asm volatile("red.release.gpu.global.add.u32 [%0], 1;"
                             :: "l"(barp) : "memory");
                unsigned target = (unsigned)(t + 1) * 32u;
                unsigned v;
                while (true) {
                    asm volatile("ld.acquire.gpu.global.u32 %0, [%1];"
                                 : "=r"(v) : "l"(barp) : "memory");
                    if (v >= target) break;
                    __nanosleep(20);
                }
            }
            __syncthreads();
        } else {
            out[(size_t)S_LEN * BH + (size_t)gb * HID + gj] = hval;        // h_f
            out[(size_t)S_LEN * BH + BH + (size_t)gb * HID + gj] = cval;   // c_f
        }
    }
}

// -------------------- launch ------------------------------------------------
extern "C" void kernel_launch(void* const* d_in, const int* in_sizes, int n_in,
                              void* d_out, int out_size)
{
    (void)in_sizes; (void)n_in; (void)out_size;
    const float* x   = (const float*)d_in[0];
    const float* Wxf = (const float*)d_in[1];
    const float* bxf = (const float*)d_in[2];
    const float* Whf = (const float*)d_in[3];
    const float* bhf = (const float*)d_in[4];
    const float* Wxi = (const float*)d_in[5];
    const float* bxi = (const float*)d_in[6];
    const float* Whi = (const float*)d_in[7];
    const float* bhi = (const float*)d_in[8];
    const float* Wxo = (const float*)d_in[9];
    const float* bxo = (const float*)d_in[10];
    const float* Who = (const float*)d_in[11];
    const float* bho = (const float*)d_in[12];
    const float* Wxg = (const float*)d_in[13];
    const float* bxg = (const float*)d_in[14];
    const float* Whg = (const float*)d_in[15];
    const float* bhg = (const float*)d_in[16];
    float* out = (float*)d_out;

    prep_kernel<<<(G4 * HID + 255) / 256, 256>>>(
        Wxf, Wxi, Wxo, Wxg, Whf, Whi, Who, Whg,
        bxf, bhf, bxi, bhi, bxo, bho, bxg, bhg);

    static bool attr_set = false;
    if (!attr_set) {
        cudaFuncSetAttribute(xproj_hmma,
                             cudaFuncAttributeMaxDynamicSharedMemorySize, XP_SMEM);
        attr_set = true;
    }
    dim3 gproj(G4 / XN, (S_LEN * BATCH) / XM);
    xproj_hmma<<<gproj, 256, XP_SMEM>>>(x);

    lstm_rec_kernel<<<NCTA, 256>>>(out);
}